// round 4
// baseline (speedup 1.0000x reference)
#include <cuda_runtime.h>
#include <stdint.h>

#define NPIX 16384   // 4 * 64 * 64 pixels per handle

// Per-handle ping-pong state: (x, y, score, unused) per pixel
__device__ float4 g_st[2][2][NPIX];
__device__ float2 g_res[2][NPIX];          // [0]=res_f, [1]=res_b

// ---------------------------------------------------------------------------
// Threefry-2x32 (matches jax._src.prng.threefry2x32)
// ---------------------------------------------------------------------------
__device__ __forceinline__ uint32_t rotl32(uint32_t v, int r) {
    return (v << r) | (v >> (32 - r));
}

__device__ __forceinline__ void tf4(uint32_t& x0, uint32_t& x1,
                                    int r0, int r1, int r2, int r3) {
    x0 += x1; x1 = rotl32(x1, r0); x1 ^= x0;
    x0 += x1; x1 = rotl32(x1, r1); x1 ^= x0;
    x0 += x1; x1 = rotl32(x1, r2); x1 ^= x0;
    x0 += x1; x1 = rotl32(x1, r3); x1 ^= x0;
}

__device__ __forceinline__ void threefry2x32(uint32_t k0, uint32_t k1,
                                             uint32_t c0, uint32_t c1,
                                             uint32_t& o0, uint32_t& o1) {
    uint32_t ks2 = k0 ^ k1 ^ 0x1BD11BDAu;
    uint32_t x0 = c0 + k0;
    uint32_t x1 = c1 + k1;
    tf4(x0, x1, 13, 15, 26, 6);   x0 += k1;  x1 += ks2 + 1u;
    tf4(x0, x1, 17, 29, 16, 24);  x0 += ks2; x1 += k0  + 2u;
    tf4(x0, x1, 13, 15, 26, 6);   x0 += k0;  x1 += k1  + 3u;
    tf4(x0, x1, 17, 29, 16, 24);  x0 += k1;  x1 += ks2 + 4u;
    tf4(x0, x1, 13, 15, 26, 6);   x0 += ks2; x1 += k0  + 5u;
    o0 = x0; o1 = x1;
}

// Subkey for (handle fwd/bwd, random-search index 0..2)
__device__ __forceinline__ void get_rs_key(int fwd, int rs,
                                           uint32_t& K0, uint32_t& K1) {
    uint32_t a0, b0, a1, b1;
    threefry2x32(0u, 42u, 0u, 2u, a0, b0);
    threefry2x32(0u, 42u, 1u, 3u, a1, b1);
    uint32_t hk0 = fwd ? a0 : b0;
    uint32_t hk1 = fwd ? a1 : b1;

    uint32_t p0a, p0b, p1a, p1b, p2a, p2b;
    threefry2x32(hk0, hk1, 0u, 3u, p0a, p0b);
    threefry2x32(hk0, hk1, 1u, 4u, p1a, p1b);
    threefry2x32(hk0, hk1, 2u, 5u, p2a, p2b);
    if (rs == 0)      { K0 = p0a; K1 = p1a; }
    else if (rs == 1) { K0 = p2a; K1 = p0b; }
    else              { K0 = p1b; K1 = p2b; }
}

// random bits for flat element index e in [0, 32768): pairs (e, e+16384)
__device__ __forceinline__ uint32_t random_bits(uint32_t K0, uint32_t K1, uint32_t e) {
    uint32_t o0, o1;
    if (e < 16384u) { threefry2x32(K0, K1, e, e + 16384u, o0, o1); return o0; }
    else            { threefry2x32(K0, K1, e - 16384u, e, o0, o1); return o1; }
}

// jax.random.normal: uniform via mantissa bits, then sqrt(2)*erfinv (XLA Giles poly)
__device__ __forceinline__ float normal_from_bits(uint32_t bits) {
    float f = __uint_as_float((bits >> 9) | 0x3f800000u) - 1.0f; // [0,1)
    const float lo = -0.99999994f;
    float u = fmaxf(lo, f * 2.0f + lo);
    float w = -log1pf(-u * u);
    float p;
    if (w < 5.0f) {
        w = w - 2.5f;
        p = 2.81022636e-08f;
        p = 3.43273939e-07f + p * w;
        p = -3.5233877e-06f + p * w;
        p = -4.39150654e-06f + p * w;
        p = 0.00021858087f + p * w;
        p = -0.00125372503f + p * w;
        p = -0.00417768164f + p * w;
        p = 0.246640727f + p * w;
        p = 1.50140941f + p * w;
    } else {
        w = sqrtf(w) - 3.0f;
        p = -0.000200214257f;
        p = 0.000100950558f + p * w;
        p = 0.00134934322f + p * w;
        p = -0.00367342844f + p * w;
        p = 0.00573950773f + p * w;
        p = -0.0076224613f + p * w;
        p = 0.00943887047f + p * w;
        p = 1.00167406f + p * w;
        p = 2.83297682f + p * w;
    }
    return 1.41421356f * (p * u);
}

// ---------------------------------------------------------------------------
// 4-lane bilinear score: lane q of the pixel group loads corner q and
// computes its weighted term (v * wx') * wy' exactly as the reference;
// reduce4 sums the 4 terms in the reference's left-to-right order.
// ---------------------------------------------------------------------------
__device__ __forceinline__ float corner_term(const float* __restrict__ base,
                                             int sy, int sx, float x, float y,
                                             int q) {
    float x0f = floorf(x), y0f = floorf(y);
    float wx = x - x0f, wy = y - y0f;
    int x0i = min(max((int)x0f, 0), 63);
    int x1i = min(x0i + 1, 63);
    int y0i = min(max((int)y0f, 0), 63);
    int y1i = min(y0i + 1, 63);
    int  xi  = (q & 1) ? x1i : x0i;
    int  yi  = (q & 2) ? y1i : y0i;
    float wxt = (q & 1) ? wx : 1.0f - wx;
    float wyt = (q & 2) ? wy : 1.0f - wy;
    return (__ldg(base + yi * sy + xi * sx) * wxt) * wyt;
}

__device__ __forceinline__ float reduce4(float t, int gbase) {
    float t0 = __shfl_sync(0xffffffffu, t, gbase + 0);
    float t1 = __shfl_sync(0xffffffffu, t, gbase + 1);
    float t2 = __shfl_sync(0xffffffffu, t, gbase + 2);
    float t3 = __shfl_sync(0xffffffffu, t, gbase + 3);
    return ((t0 + t1) + t2) + t3;   // v00 + v01 + v10 + v11 order
}

// ---------------------------------------------------------------------------
// Fused stage kernel: propagate (+ random search unless last stage).
// Grid = 512 blocks x 256 threads; 4 lanes per pixel.
// Blocks [0,256)=forward, [256,512)=backward.
// ---------------------------------------------------------------------------
__global__ void __launch_bounds__(256)
stage_kernel(const float* __restrict__ mf, const float* __restrict__ mb,
             const float* __restrict__ corr,
             const float4* __restrict__ srcF, float4* __restrict__ dstF,
             const float4* __restrict__ srcB, float4* __restrict__ dstB,
             int dx, int dy, int rsIdx, int stage0, int last) {
    int hid   = blockIdx.x >> 8;
    int p     = ((blockIdx.x & 255) << 6) | (threadIdx.x >> 2);
    int q     = threadIdx.x & 3;
    int gbase = (threadIdx.x & 31) & ~3;
    int b = p >> 12, h = (p >> 6) & 63, w = p & 63;
    int fwd = (hid == 0);

    int sy, sx;
    const float* base;
    if (fwd) { sy = 64; sx = 1; base = corr + (size_t)p * 4096; }
    else     { sy = 262144; sx = 4096; base = corr + (size_t)b * 16777216 + h * 64 + w; }

    const float4* src = fwd ? srcF : srcB;
    float4*       dst = fwd ? dstF : dstB;
    const float*  m   = fwd ? mf : mb;

    // neighbor pixel indices
    int ph = (p & ~63) | ((w - dx) & 63);
    int pv = (b << 12) | (((h - dy) & 63) << 6) | w;

    float2 cur, ch, cv;
    float cur_s;

    if (stage0) {
        int mb8 = b * 8192;
        cur = make_float2(m[mb8 + (p  & 4095)], m[mb8 + 4096 + (p  & 4095)]);
        ch  = make_float2(m[mb8 + (ph & 4095)], m[mb8 + 4096 + (ph & 4095)]);
        cv  = make_float2(m[mb8 + (pv & 4095)], m[mb8 + 4096 + (pv & 4095)]);
        // clamp candidates
        ch.x = fminf(fmaxf(ch.x + (float)dx, 0.0f), 63.0f);
        ch.y = fminf(fmaxf(ch.y, 0.0f), 63.0f);
        cv.y = fminf(fmaxf(cv.y + (float)dy, 0.0f), 63.0f);
        cv.x = fminf(fmaxf(cv.x, 0.0f), 63.0f);
        // issue all 3 corner loads, then reduce
        float tC = corner_term(base, sy, sx, cur.x, cur.y, q);
        float tH = corner_term(base, sy, sx, ch.x,  ch.y,  q);
        float tV = corner_term(base, sy, sx, cv.x,  cv.y,  q);
        cur_s    = reduce4(tC, gbase);
        float sH = reduce4(tH, gbase);
        float sV = reduce4(tV, gbase);
        if (sH > cur_s) { cur = ch; cur_s = sH; }
        if (sV > cur_s) { cur = cv; cur_s = sV; }
    } else {
        float4 st = src[p];
        float4 sh = src[ph];
        float4 sv = src[pv];
        cur = make_float2(st.x, st.y); cur_s = st.z;
        ch  = make_float2(sh.x, sh.y);
        cv  = make_float2(sv.x, sv.y);
        ch.x = fminf(fmaxf(ch.x + (float)dx, 0.0f), 63.0f);
        ch.y = fminf(fmaxf(ch.y, 0.0f), 63.0f);
        cv.y = fminf(fmaxf(cv.y + (float)dy, 0.0f), 63.0f);
        cv.x = fminf(fmaxf(cv.x, 0.0f), 63.0f);
        float tH = corner_term(base, sy, sx, ch.x, ch.y, q);
        float tV = corner_term(base, sy, sx, cv.x, cv.y, q);
        float sH = reduce4(tH, gbase);
        float sV = reduce4(tV, gbase);
        if (sH > cur_s) { cur = ch; cur_s = sH; }
        if (sV > cur_s) { cur = cv; cur_s = sV; }
    }

    if (last) {
        if (q == 0) g_res[hid][p] = cur;
        return;
    }

    // ---- random search (decisions uniform across the 4 lanes) ----
    uint32_t K0, K1;
    get_rs_key(fwd, rsIdx, K0, K1);
    float n0 = normal_from_bits(random_bits(K0, K1, 2u * (uint32_t)p));
    float n1 = normal_from_bits(random_bits(K0, K1, 2u * (uint32_t)p + 1u));
    float2 cn;
    cn.x = fminf(fmaxf(cur.x + 3.0f * n0, 0.0f), 63.0f);
    cn.y = fminf(fmaxf(cur.y + 3.0f * n1, 0.0f), 63.0f);
    float tN = corner_term(base, sy, sx, cn.x, cn.y, q);
    float new_s = reduce4(tN, gbase);
    if (new_s - 1.0f * cur_s > 0.0f) { cur = cn; cur_s = new_s; }

    if (q == 0) dst[p] = make_float4(cur.x, cur.y, cur_s, 0.0f);
}

// ---------------------------------------------------------------------------
// Forward-backward consistency + output transpose (g_res is L2-resident)
// ---------------------------------------------------------------------------
__global__ void __launch_bounds__(256)
final_kernel(const float* __restrict__ mf, float* __restrict__ out) {
    int p = blockIdx.x * blockDim.x + threadIdx.x;
    int b = p >> 12, hw = p & 4095;

    float2 f = g_res[0][p];
    float x0f = floorf(f.x), y0f = floorf(f.y);
    float wx = f.x - x0f, wy = f.y - y0f;
    int x0i = min(max((int)x0f, 0), 63);
    int x1i = min(x0i + 1, 63);
    int y0i = min(max((int)y0f, 0), 63);
    int y1i = min(y0i + 1, 63);
    const float2* img = g_res[1] + (b << 12);
    float2 v00 = img[y0i * 64 + x0i];
    float2 v01 = img[y0i * 64 + x1i];
    float2 v10 = img[y1i * 64 + x0i];
    float2 v11 = img[y1i * 64 + x1i];
    float cx = v00.x * (1.0f - wx) * (1.0f - wy) + v01.x * wx * (1.0f - wy)
             + v10.x * (1.0f - wx) * wy          + v11.x * wx * wy;
    float cy = v00.y * (1.0f - wx) * (1.0f - wy) + v01.y * wx * (1.0f - wy)
             + v10.y * (1.0f - wx) * wy          + v11.y * wx * wy;

    float diff = fmaxf(fabsf(f.x - cx), fabsf(f.y - cy));
    bool invalid = diff > 0.01f;
    float ox = invalid ? mf[b * 8192 + hw]        : f.x;
    float oy = invalid ? mf[b * 8192 + 4096 + hw] : f.y;
    out[b * 8192 + hw]        = ox;
    out[b * 8192 + 4096 + hw] = oy;
}

// ---------------------------------------------------------------------------
// Host launcher: 5 launches, both handles concurrent inside each stage kernel
// ---------------------------------------------------------------------------
extern "C" void kernel_launch(void* const* d_in, const int* in_sizes, int n_in,
                              void* d_out, int out_size) {
    const float* mf   = (const float*)d_in[0];
    const float* mb   = (const float*)d_in[1];
    const float* corr = (const float*)d_in[2];
    float* out = (float*)d_out;

    float4* st;
    cudaGetSymbolAddress((void**)&st, g_st);
    float4* F0 = st;                 // g_st[0][0]
    float4* F1 = st + NPIX;          // g_st[0][1]
    float4* B0 = st + 2 * NPIX;      // g_st[1][0]
    float4* B1 = st + 3 * NPIX;      // g_st[1][1]

    // stage 0: init + prop(1,1)  + rs0   (neighbors read straight from m)
    stage_kernel<<<512, 256>>>(mf, mb, corr, nullptr, F0, nullptr, B0,
                               1, 1, 0, 1, 0);
    // stage 1: prop(-1,-1) + rs1
    stage_kernel<<<512, 256>>>(mf, mb, corr, F0, F1, B0, B1,
                               -1, -1, 1, 0, 0);
    // stage 2: prop(-1,1) + rs2
    stage_kernel<<<512, 256>>>(mf, mb, corr, F1, F0, B1, B0,
                               -1, 1, 2, 0, 0);
    // stage 3: prop(1,-1) -> g_res
    stage_kernel<<<512, 256>>>(mf, mb, corr, F0, nullptr, B0, nullptr,
                               1, -1, 0, 0, 1);
    // consistency + output
    final_kernel<<<64, 256>>>(mf, out);
}

// round 5
// speedup vs baseline: 1.3756x; 1.3756x over previous
#include <cuda_runtime.h>
#include <stdint.h>

#define NPIX 16384   // 4 * 64 * 64 pixels per handle

__device__ float2 g_res[2][NPIX];          // [0]=res_f, [1]=res_b

struct RsKeys { uint32_t K0[2][3]; uint32_t K1[2][3]; };

// ---------------------------------------------------------------------------
// Threefry-2x32 (matches jax._src.prng.threefry2x32) — host + device
// ---------------------------------------------------------------------------
__host__ __device__ __forceinline__ uint32_t rotl32(uint32_t v, int r) {
    return (v << r) | (v >> (32 - r));
}

__host__ __device__ __forceinline__ void tf4(uint32_t& x0, uint32_t& x1,
                                             int r0, int r1, int r2, int r3) {
    x0 += x1; x1 = rotl32(x1, r0); x1 ^= x0;
    x0 += x1; x1 = rotl32(x1, r1); x1 ^= x0;
    x0 += x1; x1 = rotl32(x1, r2); x1 ^= x0;
    x0 += x1; x1 = rotl32(x1, r3); x1 ^= x0;
}

__host__ __device__ __forceinline__ void threefry2x32(uint32_t k0, uint32_t k1,
                                                      uint32_t c0, uint32_t c1,
                                                      uint32_t& o0, uint32_t& o1) {
    uint32_t ks2 = k0 ^ k1 ^ 0x1BD11BDAu;
    uint32_t x0 = c0 + k0;
    uint32_t x1 = c1 + k1;
    tf4(x0, x1, 13, 15, 26, 6);   x0 += k1;  x1 += ks2 + 1u;
    tf4(x0, x1, 17, 29, 16, 24);  x0 += ks2; x1 += k0  + 2u;
    tf4(x0, x1, 13, 15, 26, 6);   x0 += k0;  x1 += k1  + 3u;
    tf4(x0, x1, 17, 29, 16, 24);  x0 += k1;  x1 += ks2 + 4u;
    tf4(x0, x1, 13, 15, 26, 6);   x0 += ks2; x1 += k0  + 5u;
    o0 = x0; o1 = x1;
}

// random bits for flat element index e in [0, 32768): pairs (e, e+16384)
__device__ __forceinline__ uint32_t random_bits(uint32_t K0, uint32_t K1, uint32_t e) {
    uint32_t o0, o1;
    if (e < 16384u) { threefry2x32(K0, K1, e, e + 16384u, o0, o1); return o0; }
    else            { threefry2x32(K0, K1, e - 16384u, e, o0, o1); return o1; }
}

// jax.random.normal: uniform via mantissa bits, then sqrt(2)*erfinv (XLA Giles poly)
__device__ __forceinline__ float normal_from_bits(uint32_t bits) {
    float f = __uint_as_float((bits >> 9) | 0x3f800000u) - 1.0f; // [0,1)
    const float lo = -0.99999994f;
    float u = fmaxf(lo, f * 2.0f + lo);
    float w = -log1pf(-u * u);
    float p;
    if (w < 5.0f) {
        w = w - 2.5f;
        p = 2.81022636e-08f;
        p = 3.43273939e-07f + p * w;
        p = -3.5233877e-06f + p * w;
        p = -4.39150654e-06f + p * w;
        p = 0.00021858087f + p * w;
        p = -0.00125372503f + p * w;
        p = -0.00417768164f + p * w;
        p = 0.246640727f + p * w;
        p = 1.50140941f + p * w;
    } else {
        w = sqrtf(w) - 3.0f;
        p = -0.000200214257f;
        p = 0.000100950558f + p * w;
        p = 0.00134934322f + p * w;
        p = -0.00367342844f + p * w;
        p = 0.00573950773f + p * w;
        p = -0.0076224613f + p * w;
        p = 0.00943887047f + p * w;
        p = 1.00167406f + p * w;
        p = 2.83297682f + p * w;
    }
    return 1.41421356f * (p * u);
}

// ---------------------------------------------------------------------------
// Bilinear score (exact reference op order)
// forward:  base = corr + p*4096,              sy=64,     sx=1
// backward: base = corr + b*16M + h*64 + w,    sy=262144, sx=4096
// ---------------------------------------------------------------------------
__device__ __forceinline__ float score(const float* __restrict__ base,
                                       int sy, int sx, float x, float y) {
    float x0f = floorf(x), y0f = floorf(y);
    float wx = x - x0f, wy = y - y0f;
    int x0i = min(max((int)x0f, 0), 63);
    int x1i = min(x0i + 1, 63);
    int y0i = min(max((int)y0f, 0), 63);
    int y1i = min(y0i + 1, 63);
    float v00 = __ldg(base + y0i * sy + x0i * sx);
    float v01 = __ldg(base + y0i * sy + x1i * sx);
    float v10 = __ldg(base + y1i * sy + x0i * sx);
    float v11 = __ldg(base + y1i * sy + x1i * sx);
    return v00 * (1.0f - wx) * (1.0f - wy) + v01 * wx * (1.0f - wy)
         + v10 * (1.0f - wx) * wy          + v11 * wx * wy;
}

// ---------------------------------------------------------------------------
// Fully-fused PatchMatch kernel.
// Grid = 128 blocks x 384 threads. Block -> (handle, batch, 16x16 tile).
// All 4 propagate(+rs) stages run inside the block over a shrinking halo:
//   R0: w,h in [-1,17]  (19x19, stage0 also does rs0)
//   R1: w,h in [-1,16]  (18x18, rs1)
//   R2: w in [-1,15], h in [0,16]  (17x17, rs2)
//   R3: w,h in [0,16)   (16x16, final propagate -> g_res)
// Wraparound (mod 64) exactly matches jnp.roll semantics.
// ---------------------------------------------------------------------------
__global__ void __launch_bounds__(384)
fused_kernel(const float* __restrict__ mf, const float* __restrict__ mb,
             const float* __restrict__ corr, RsKeys keys) {
    __shared__ float4 st[19 * 19];   // state (x, y, score) indexed by R0 coords

    int bi   = blockIdx.x;
    int hid  = bi >> 6;               // 0 = forward, 1 = backward
    int rem  = bi & 63;
    int b    = rem >> 4;
    int tile = rem & 15;
    int th0  = (tile >> 2) << 4;      // tile origin h
    int tw0  = (tile & 3) << 4;       // tile origin w
    int tid  = threadIdx.x;
    int fwd  = (hid == 0);

    const float* m = fwd ? mf : mb;
    const int mb8 = b * 8192;

    const int DX[4]   = { 1, -1, -1,  1 };
    const int DY[4]   = { 1, -1,  1, -1 };
    const int SZW[4]  = { 19, 18, 17, 16 };
    const int SZH[4]  = { 19, 18, 17, 16 };
    const int OFFW[4] = { -1, -1, -1, 0 };
    const int OFFH[4] = { -1, -1,  0, 0 };

    #pragma unroll
    for (int s = 0; s < 4; s++) {
        int n = SZW[s] * SZH[s];
        bool active = tid < n;
        float4 outst = make_float4(0.f, 0.f, 0.f, 0.f);
        int lw = 0, lh = 0;
        float2 res;

        if (active) {
            lw = tid % SZW[s] + OFFW[s];
            lh = tid / SZW[s] + OFFH[s];
            int wg = (tw0 + lw) & 63;
            int hg = (th0 + lh) & 63;
            int p  = (b << 12) | (hg << 6) | wg;

            int sy, sx;
            const float* base;
            if (fwd) { sy = 64; sx = 1; base = corr + (size_t)p * 4096; }
            else     { sy = 262144; sx = 4096;
                       base = corr + (size_t)b * 16777216 + hg * 64 + wg; }

            int dx = DX[s], dy = DY[s];
            float2 cur, ch, cv;
            float cur_s;

            if (s == 0) {
                int hwS = (hg << 6) | wg;
                int hwH = (hg << 6) | ((wg - dx) & 63);
                int hwV = (((hg - dy) & 63) << 6) | wg;
                cur = make_float2(m[mb8 + hwS], m[mb8 + 4096 + hwS]);
                ch  = make_float2(m[mb8 + hwH], m[mb8 + 4096 + hwH]);
                cv  = make_float2(m[mb8 + hwV], m[mb8 + 4096 + hwV]);
                // clamp candidates
                ch.x = fminf(fmaxf(ch.x + (float)dx, 0.0f), 63.0f);
                ch.y = fminf(fmaxf(ch.y, 0.0f), 63.0f);
                cv.y = fminf(fmaxf(cv.y + (float)dy, 0.0f), 63.0f);
                cv.x = fminf(fmaxf(cv.x, 0.0f), 63.0f);
                cur_s    = score(base, sy, sx, cur.x, cur.y);
                float sH = score(base, sy, sx, ch.x,  ch.y);
                float sV = score(base, sy, sx, cv.x,  cv.y);
                if (sH > cur_s) { cur = ch; cur_s = sH; }
                if (sV > cur_s) { cur = cv; cur_s = sV; }
            } else {
                // read previous-stage state from smem (regions verified nested)
                float4 s0 = st[(lh + 1) * 19 + (lw + 1)];
                float4 sh = st[(lh + 1) * 19 + (lw - dx + 1)];
                float4 sv = st[(lh - dy + 1) * 19 + (lw + 1)];
                cur = make_float2(s0.x, s0.y); cur_s = s0.z;
                ch  = make_float2(sh.x, sh.y);
                cv  = make_float2(sv.x, sv.y);
                ch.x = fminf(fmaxf(ch.x + (float)dx, 0.0f), 63.0f);
                ch.y = fminf(fmaxf(ch.y, 0.0f), 63.0f);
                cv.y = fminf(fmaxf(cv.y + (float)dy, 0.0f), 63.0f);
                cv.x = fminf(fmaxf(cv.x, 0.0f), 63.0f);
                float sH = score(base, sy, sx, ch.x, ch.y);
                float sV = score(base, sy, sx, cv.x, cv.y);
                if (sH > cur_s) { cur = ch; cur_s = sH; }
                if (sV > cur_s) { cur = cv; cur_s = sV; }
            }

            if (s < 3) {
                // ---- random search s ----
                uint32_t K0 = keys.K0[hid][s], K1 = keys.K1[hid][s];
                float n0 = normal_from_bits(random_bits(K0, K1, 2u * (uint32_t)p));
                float n1 = normal_from_bits(random_bits(K0, K1, 2u * (uint32_t)p + 1u));
                float2 cn;
                cn.x = fminf(fmaxf(cur.x + 3.0f * n0, 0.0f), 63.0f);
                cn.y = fminf(fmaxf(cur.y + 3.0f * n1, 0.0f), 63.0f);
                float new_s = score(base, sy, sx, cn.x, cn.y);
                if (new_s - 1.0f * cur_s > 0.0f) { cur = cn; cur_s = new_s; }
                outst = make_float4(cur.x, cur.y, cur_s, 0.0f);
            } else {
                res = cur;
            }
        }

        __syncthreads();   // all prev-stage reads complete before overwrite
        if (active) {
            if (s < 3) st[(lh + 1) * 19 + (lw + 1)] = outst;
            else {
                int wg = (tw0 + lw) & 63;
                int hg = (th0 + lh) & 63;
                g_res[hid][(b << 12) | (hg << 6) | wg] = res;
            }
        }
        __syncthreads();
    }
}

// ---------------------------------------------------------------------------
// Forward-backward consistency + output transpose
// ---------------------------------------------------------------------------
__global__ void __launch_bounds__(256)
final_kernel(const float* __restrict__ mf, float* __restrict__ out) {
    int p = blockIdx.x * blockDim.x + threadIdx.x;
    int b = p >> 12, hw = p & 4095;

    float2 f = g_res[0][p];
    float x0f = floorf(f.x), y0f = floorf(f.y);
    float wx = f.x - x0f, wy = f.y - y0f;
    int x0i = min(max((int)x0f, 0), 63);
    int x1i = min(x0i + 1, 63);
    int y0i = min(max((int)y0f, 0), 63);
    int y1i = min(y0i + 1, 63);
    const float2* img = g_res[1] + (b << 12);
    float2 v00 = img[y0i * 64 + x0i];
    float2 v01 = img[y0i * 64 + x1i];
    float2 v10 = img[y1i * 64 + x0i];
    float2 v11 = img[y1i * 64 + x1i];
    float cx = v00.x * (1.0f - wx) * (1.0f - wy) + v01.x * wx * (1.0f - wy)
             + v10.x * (1.0f - wx) * wy          + v11.x * wx * wy;
    float cy = v00.y * (1.0f - wx) * (1.0f - wy) + v01.y * wx * (1.0f - wy)
             + v10.y * (1.0f - wx) * wy          + v11.y * wx * wy;

    float diff = fmaxf(fabsf(f.x - cx), fabsf(f.y - cy));
    bool invalid = diff > 0.01f;
    float ox = invalid ? mf[b * 8192 + hw]        : f.x;
    float oy = invalid ? mf[b * 8192 + 4096 + hw] : f.y;
    out[b * 8192 + hw]        = ox;
    out[b * 8192 + 4096 + hw] = oy;
}

// ---------------------------------------------------------------------------
// Host launcher: keys computed on host (deterministic), 2 launches total
// ---------------------------------------------------------------------------
extern "C" void kernel_launch(void* const* d_in, const int* in_sizes, int n_in,
                              void* d_out, int out_size) {
    const float* mf   = (const float*)d_in[0];
    const float* mb   = (const float*)d_in[1];
    const float* corr = (const float*)d_in[2];
    float* out = (float*)d_out;

    // Derive the 6 random-search subkeys on the host:
    // root key(42) -> split into (kf, kb) -> each split into 3.
    RsKeys keys;
    uint32_t a0, b0, a1, b1;
    threefry2x32(0u, 42u, 0u, 2u, a0, b0);
    threefry2x32(0u, 42u, 1u, 3u, a1, b1);
    for (int hid = 0; hid < 2; hid++) {
        uint32_t hk0 = (hid == 0) ? a0 : b0;
        uint32_t hk1 = (hid == 0) ? a1 : b1;
        uint32_t p0a, p0b, p1a, p1b, p2a, p2b;
        threefry2x32(hk0, hk1, 0u, 3u, p0a, p0b);
        threefry2x32(hk0, hk1, 1u, 4u, p1a, p1b);
        threefry2x32(hk0, hk1, 2u, 5u, p2a, p2b);
        keys.K0[hid][0] = p0a; keys.K1[hid][0] = p1a;
        keys.K0[hid][1] = p2a; keys.K1[hid][1] = p0b;
        keys.K0[hid][2] = p1b; keys.K1[hid][2] = p2b;
    }

    fused_kernel<<<128, 384>>>(mf, mb, corr, keys);
    final_kernel<<<64, 256>>>(mf, out);
}

// round 9
// speedup vs baseline: 1.4184x; 1.0311x over previous
#include <cuda_runtime.h>
#include <stdint.h>

#define NPIX 16384   // 4 * 64 * 64 pixels per handle

__device__ float2 g_res[2][NPIX];          // [0]=res_f, [1]=res_b

struct RsKeys { uint32_t K0[2][3]; uint32_t K1[2][3]; };

// ---------------------------------------------------------------------------
// Threefry-2x32 (matches jax._src.prng.threefry2x32) — host + device
// ---------------------------------------------------------------------------
__host__ __device__ __forceinline__ uint32_t rotl32(uint32_t v, int r) {
    return (v << r) | (v >> (32 - r));
}

__host__ __device__ __forceinline__ void tf4(uint32_t& x0, uint32_t& x1,
                                             int r0, int r1, int r2, int r3) {
    x0 += x1; x1 = rotl32(x1, r0); x1 ^= x0;
    x0 += x1; x1 = rotl32(x1, r1); x1 ^= x0;
    x0 += x1; x1 = rotl32(x1, r2); x1 ^= x0;
    x0 += x1; x1 = rotl32(x1, r3); x1 ^= x0;
}

__host__ __device__ __forceinline__ void threefry2x32(uint32_t k0, uint32_t k1,
                                                      uint32_t c0, uint32_t c1,
                                                      uint32_t& o0, uint32_t& o1) {
    uint32_t ks2 = k0 ^ k1 ^ 0x1BD11BDAu;
    uint32_t x0 = c0 + k0;
    uint32_t x1 = c1 + k1;
    tf4(x0, x1, 13, 15, 26, 6);   x0 += k1;  x1 += ks2 + 1u;
    tf4(x0, x1, 17, 29, 16, 24);  x0 += ks2; x1 += k0  + 2u;
    tf4(x0, x1, 13, 15, 26, 6);   x0 += k0;  x1 += k1  + 3u;
    tf4(x0, x1, 17, 29, 16, 24);  x0 += k1;  x1 += ks2 + 4u;
    tf4(x0, x1, 13, 15, 26, 6);   x0 += ks2; x1 += k0  + 5u;
    o0 = x0; o1 = x1;
}

// random bits for flat element index e in [0, 32768): pairs (e, e+16384)
__device__ __forceinline__ uint32_t random_bits(uint32_t K0, uint32_t K1, uint32_t e) {
    uint32_t o0, o1;
    if (e < 16384u) { threefry2x32(K0, K1, e, e + 16384u, o0, o1); return o0; }
    else            { threefry2x32(K0, K1, e - 16384u, e, o0, o1); return o1; }
}

// jax.random.normal: uniform via mantissa bits, then sqrt(2)*erfinv (XLA Giles poly)
__device__ __forceinline__ float normal_from_bits(uint32_t bits) {
    float f = __uint_as_float((bits >> 9) | 0x3f800000u) - 1.0f; // [0,1)
    const float lo = -0.99999994f;
    float u = fmaxf(lo, f * 2.0f + lo);
    float w = -log1pf(-u * u);
    float p;
    if (w < 5.0f) {
        w = w - 2.5f;
        p = 2.81022636e-08f;
        p = 3.43273939e-07f + p * w;
        p = -3.5233877e-06f + p * w;
        p = -4.39150654e-06f + p * w;
        p = 0.00021858087f + p * w;
        p = -0.00125372503f + p * w;
        p = -0.00417768164f + p * w;
        p = 0.246640727f + p * w;
        p = 1.50140941f + p * w;
    } else {
        w = sqrtf(w) - 3.0f;
        p = -0.000200214257f;
        p = 0.000100950558f + p * w;
        p = 0.00134934322f + p * w;
        p = -0.00367342844f + p * w;
        p = 0.00573950773f + p * w;
        p = -0.0076224613f + p * w;
        p = 0.00943887047f + p * w;
        p = 1.00167406f + p * w;
        p = 2.83297682f + p * w;
    }
    return 1.41421356f * (p * u);
}

// ---------------------------------------------------------------------------
// Bilinear score (exact reference op order)
// forward:  base = corr + p*4096,              sy=64,     sx=1
// backward: base = corr + b*16M + h*64 + w,    sy=262144, sx=4096
// ---------------------------------------------------------------------------
__device__ __forceinline__ float score(const float* __restrict__ base,
                                       int sy, int sx, float x, float y) {
    float x0f = floorf(x), y0f = floorf(y);
    float wx = x - x0f, wy = y - y0f;
    int x0i = min(max((int)x0f, 0), 63);
    int x1i = min(x0i + 1, 63);
    int y0i = min(max((int)y0f, 0), 63);
    int y1i = min(y0i + 1, 63);
    float v00 = __ldg(base + y0i * sy + x0i * sx);
    float v01 = __ldg(base + y0i * sy + x1i * sx);
    float v10 = __ldg(base + y1i * sy + x0i * sx);
    float v11 = __ldg(base + y1i * sy + x1i * sx);
    return v00 * (1.0f - wx) * (1.0f - wy) + v01 * wx * (1.0f - wy)
         + v10 * (1.0f - wx) * wy          + v11 * wx * wy;
}

// ---------------------------------------------------------------------------
// Fully-fused PatchMatch kernel (Round-5 passing structure, single buffer).
// Grid = 128 blocks x 384 threads. Block -> (handle, batch, 16x16 tile).
// Stages over shrinking halo regions:
//   R0: w,h in [-1,17]  (19x19, + rs0)
//   R1: w,h in [-1,16]  (18x18, + rs1)
//   R2: w in [-1,15], h in [0,16]  (17x17, + rs2)
//   R3: w,h in [0,16)   (16x16, final propagate -> g_res)
// Barriers (5 total, minimal set):
//   boundary after each stage's smem writes (s0->s1, s1->s2, s2->s3)
//   read->write protect inside stages 1 and 2 (same-buffer overlap)
// Stage 0 reads only global memory; stage 3 writes only g_res.
// ---------------------------------------------------------------------------
__global__ void __launch_bounds__(384)
fused_kernel(const float* __restrict__ mf, const float* __restrict__ mb,
             const float* __restrict__ corr, RsKeys keys) {
    __shared__ float4 st[19 * 19];   // state (x, y, score) indexed by R0 coords

    int bi   = blockIdx.x;
    int hid  = bi >> 6;               // 0 = forward, 1 = backward
    int rem  = bi & 63;
    int b    = rem >> 4;
    int tile = rem & 15;
    int th0  = (tile >> 2) << 4;      // tile origin h
    int tw0  = (tile & 3) << 4;       // tile origin w
    int tid  = threadIdx.x;
    int fwd  = (hid == 0);

    const float* m = fwd ? mf : mb;
    const int mb8 = b * 8192;

    const int DX[4]   = { 1, -1, -1,  1 };
    const int DY[4]   = { 1, -1,  1, -1 };
    const int SZW[4]  = { 19, 18, 17, 16 };
    const int SZH[4]  = { 19, 18, 17, 16 };
    const int OFFW[4] = { -1, -1, -1, 0 };
    const int OFFH[4] = { -1, -1,  0, 0 };

    #pragma unroll
    for (int s = 0; s < 4; s++) {
        if (s > 0) __syncthreads();   // boundary: prev stage's writes visible

        int n = SZW[s] * SZH[s];
        bool active = tid < n;
        float4 outst = make_float4(0.f, 0.f, 0.f, 0.f);
        int lw = 0, lh = 0;
        float2 res;

        if (active) {
            lw = tid % SZW[s] + OFFW[s];
            lh = tid / SZW[s] + OFFH[s];
            int wg = (tw0 + lw) & 63;
            int hg = (th0 + lh) & 63;
            int p  = (b << 12) | (hg << 6) | wg;

            int sy, sx;
            const float* base;
            if (fwd) { sy = 64; sx = 1; base = corr + (size_t)p * 4096; }
            else     { sy = 262144; sx = 4096;
                       base = corr + (size_t)b * 16777216 + hg * 64 + wg; }

            int dx = DX[s], dy = DY[s];
            float2 cur, ch, cv;
            float cur_s;

            if (s == 0) {
                int hwS = (hg << 6) | wg;
                int hwH = (hg << 6) | ((wg - dx) & 63);
                int hwV = (((hg - dy) & 63) << 6) | wg;
                cur = make_float2(m[mb8 + hwS], m[mb8 + 4096 + hwS]);
                ch  = make_float2(m[mb8 + hwH], m[mb8 + 4096 + hwH]);
                cv  = make_float2(m[mb8 + hwV], m[mb8 + 4096 + hwV]);
                ch.x = fminf(fmaxf(ch.x + (float)dx, 0.0f), 63.0f);
                ch.y = fminf(fmaxf(ch.y, 0.0f), 63.0f);
                cv.y = fminf(fmaxf(cv.y + (float)dy, 0.0f), 63.0f);
                cv.x = fminf(fmaxf(cv.x, 0.0f), 63.0f);
                cur_s    = score(base, sy, sx, cur.x, cur.y);
                float sH = score(base, sy, sx, ch.x,  ch.y);
                float sV = score(base, sy, sx, cv.x,  cv.y);
                if (sH > cur_s) { cur = ch; cur_s = sH; }
                if (sV > cur_s) { cur = cv; cur_s = sV; }
            } else {
                float4 s0 = st[(lh + 1) * 19 + (lw + 1)];
                float4 sh = st[(lh + 1) * 19 + (lw - dx + 1)];
                float4 sv = st[(lh - dy + 1) * 19 + (lw + 1)];
                cur = make_float2(s0.x, s0.y); cur_s = s0.z;
                ch  = make_float2(sh.x, sh.y);
                cv  = make_float2(sv.x, sv.y);
                ch.x = fminf(fmaxf(ch.x + (float)dx, 0.0f), 63.0f);
                ch.y = fminf(fmaxf(ch.y, 0.0f), 63.0f);
                cv.y = fminf(fmaxf(cv.y + (float)dy, 0.0f), 63.0f);
                cv.x = fminf(fmaxf(cv.x, 0.0f), 63.0f);
                float sH = score(base, sy, sx, ch.x, ch.y);
                float sV = score(base, sy, sx, cv.x, cv.y);
                if (sH > cur_s) { cur = ch; cur_s = sH; }
                if (sV > cur_s) { cur = cv; cur_s = sV; }
            }

            if (s < 3) {
                // ---- random search s ----
                uint32_t K0 = keys.K0[hid][s], K1 = keys.K1[hid][s];
                float n0 = normal_from_bits(random_bits(K0, K1, 2u * (uint32_t)p));
                float n1 = normal_from_bits(random_bits(K0, K1, 2u * (uint32_t)p + 1u));
                float2 cn;
                cn.x = fminf(fmaxf(cur.x + 3.0f * n0, 0.0f), 63.0f);
                cn.y = fminf(fmaxf(cur.y + 3.0f * n1, 0.0f), 63.0f);
                float new_s = score(base, sy, sx, cn.x, cn.y);
                if (new_s - 1.0f * cur_s > 0.0f) { cur = cn; cur_s = new_s; }
                outst = make_float4(cur.x, cur.y, cur_s, 0.0f);
            } else {
                res = cur;
            }
        }

        // read->write protect needed only when this stage both read and
        // writes the (single) smem buffer: stages 1 and 2.
        if (s == 1 || s == 2) __syncthreads();

        if (active) {
            if (s < 3) st[(lh + 1) * 19 + (lw + 1)] = outst;
            else {
                int wg = (tw0 + lw) & 63;
                int hg = (th0 + lh) & 63;
                g_res[hid][(b << 12) | (hg << 6) | wg] = res;
            }
        }
    }
}

// ---------------------------------------------------------------------------
// Forward-backward consistency + output transpose
// ---------------------------------------------------------------------------
__global__ void __launch_bounds__(256)
final_kernel(const float* __restrict__ mf, float* __restrict__ out) {
    int p = blockIdx.x * blockDim.x + threadIdx.x;
    int b = p >> 12, hw = p & 4095;

    // independent prefetch (matching_f fallback values)
    float mx = __ldg(mf + b * 8192 + hw);
    float my = __ldg(mf + b * 8192 + 4096 + hw);

    float2 f = g_res[0][p];
    float x0f = floorf(f.x), y0f = floorf(f.y);
    float wx = f.x - x0f, wy = f.y - y0f;
    int x0i = min(max((int)x0f, 0), 63);
    int x1i = min(x0i + 1, 63);
    int y0i = min(max((int)y0f, 0), 63);
    int y1i = min(y0i + 1, 63);
    const float2* img = g_res[1] + (b << 12);
    float2 v00 = img[y0i * 64 + x0i];
    float2 v01 = img[y0i * 64 + x1i];
    float2 v10 = img[y1i * 64 + x0i];
    float2 v11 = img[y1i * 64 + x1i];
    float cx = v00.x * (1.0f - wx) * (1.0f - wy) + v01.x * wx * (1.0f - wy)
             + v10.x * (1.0f - wx) * wy          + v11.x * wx * wy;
    float cy = v00.y * (1.0f - wx) * (1.0f - wy) + v01.y * wx * (1.0f - wy)
             + v10.y * (1.0f - wx) * wy          + v11.y * wx * wy;

    float diff = fmaxf(fabsf(f.x - cx), fabsf(f.y - cy));
    bool invalid = diff > 0.01f;
    out[b * 8192 + hw]        = invalid ? mx : f.x;
    out[b * 8192 + 4096 + hw] = invalid ? my : f.y;
}

// ---------------------------------------------------------------------------
// Host launcher: keys on host; 2 plain launches
// ---------------------------------------------------------------------------
extern "C" void kernel_launch(void* const* d_in, const int* in_sizes, int n_in,
                              void* d_out, int out_size) {
    const float* mf   = (const float*)d_in[0];
    const float* mb   = (const float*)d_in[1];
    const float* corr = (const float*)d_in[2];
    float* out = (float*)d_out;

    // Derive the 6 random-search subkeys on the host:
    // root key(42) -> split into (kf, kb) -> each split into 3.
    RsKeys keys;
    uint32_t a0, b0, a1, b1;
    threefry2x32(0u, 42u, 0u, 2u, a0, b0);
    threefry2x32(0u, 42u, 1u, 3u, a1, b1);
    for (int hid = 0; hid < 2; hid++) {
        uint32_t hk0 = (hid == 0) ? a0 : b0;
        uint32_t hk1 = (hid == 0) ? a1 : b1;
        uint32_t p0a, p0b, p1a, p1b, p2a, p2b;
        threefry2x32(hk0, hk1, 0u, 3u, p0a, p0b);
        threefry2x32(hk0, hk1, 1u, 4u, p1a, p1b);
        threefry2x32(hk0, hk1, 2u, 5u, p2a, p2b);
        keys.K0[hid][0] = p0a; keys.K1[hid][0] = p1a;
        keys.K0[hid][1] = p2a; keys.K1[hid][1] = p0b;
        keys.K0[hid][2] = p1b; keys.K1[hid][2] = p2b;
    }

    fused_kernel<<<128, 384>>>(mf, mb, corr, keys);
    final_kernel<<<64, 256>>>(mf, out);
}